// round 1
// baseline (speedup 1.0000x reference)
#include <cuda_runtime.h>

typedef unsigned long long ull;

#define IMG_W 512
#define IMG_H 512
#define NPLANES 48          // 16 batch * 3 channels
#define STRIPS 8
#define STRIP_ROWS 66       // 6*11 rows per block (rows >= 512 computed but not accumulated)
#define NBLOCKS (NPLANES * STRIPS)   // 384
#define NTHREADS 256        // each thread owns 2 adjacent columns (float2 packed)
#define ROWU (IMG_W / 2)    // 256 ull (float2) per image row

#define SSIM_C1 0.0001f
#define SSIM_C2 0.0009f

// 1D gaussian (sigma=1.5, 11 taps, normalized). Literals so ptxas emits FFMA-imm (rt=1).
#define G0 0.00102836f
#define G1 0.00759863f
#define G2 0.03600078f
#define G3 0.10936075f
#define G4 0.21300559f
#define G5 0.26601179f

__device__ double g_partials[NBLOCKS];

__device__ __forceinline__ ull pack2(float x, float y) {
    ull r; asm("mov.b64 %0, {%1,%2};" : "=l"(r) : "f"(x), "f"(y)); return r;
}
__device__ __forceinline__ ull mul2(ull a, ull b) {
    ull d; asm("mul.rn.f32x2 %0, %1, %2;" : "=l"(d) : "l"(a), "l"(b)); return d;
}
__device__ __forceinline__ ull fma2(ull a, ull b, ull c) {
    ull d; asm("fma.rn.f32x2 %0, %1, %2, %3;" : "=l"(d) : "l"(a), "l"(b), "l"(c)); return d;
}

// Horizontal 11-tap conv for 2 adjacent output columns (c=2t, c+1) from a shared V row.
// V row layout: element index e holds cols (2(e-4), 2(e-4)+1); halo elements are zero.
__device__ __forceinline__ void hconv(const float2* __restrict__ row, int t,
                                      float& o0, float& o1) {
    float e[14];
#pragma unroll
    for (int j = 0; j < 7; ++j) {
        float2 v = row[t + 1 + j];   // e[i] = V[c - 6 + i]
        e[2 * j] = v.x;
        e[2 * j + 1] = v.y;
    }
    float a = G0 * e[1];
    a = fmaf(G1, e[2], a);  a = fmaf(G2, e[3], a);  a = fmaf(G3, e[4], a);
    a = fmaf(G4, e[5], a);  a = fmaf(G5, e[6], a);  a = fmaf(G4, e[7], a);
    a = fmaf(G3, e[8], a);  a = fmaf(G2, e[9], a);  a = fmaf(G1, e[10], a);
    a = fmaf(G0, e[11], a);
    float b = G0 * e[2];
    b = fmaf(G1, e[3], b);  b = fmaf(G2, e[4], b);  b = fmaf(G3, e[5], b);
    b = fmaf(G4, e[6], b);  b = fmaf(G5, e[7], b);  b = fmaf(G4, e[8], b);
    b = fmaf(G3, e[9], b);  b = fmaf(G2, e[10], b); b = fmaf(G1, e[11], b);
    b = fmaf(G0, e[12], b);
    o0 = a; o1 = b;
}

__device__ __forceinline__ float ssim_px(float mu1, float mu2, float exx,
                                         float eyy, float exy) {
    float m11 = mu1 * mu1;
    float m22 = mu2 * mu2;
    float m12 = mu1 * mu2;
    float s1  = exx - m11;
    float s2  = eyy - m22;
    float s12 = exy - m12;
    float num = fmaf(2.0f, m12, SSIM_C1) * fmaf(2.0f, s12, SSIM_C2);
    float den = ((m11 + m22) + SSIM_C1) * ((s1 + s2) + SSIM_C2);
    return __fdividef(num, den);
}

__global__ void __launch_bounds__(NTHREADS, 1)
ssim_main(const float* __restrict__ img1, const float* __restrict__ img2) {
    __shared__ ull Vs[2][5][264];            // double-buffered V rows, 5 fields, halo-padded
    __shared__ float wsums[NTHREADS / 32];

    const int bx = blockIdx.x;
    const int plane = bx >> 3;
    const int strip = bx & 7;
    const int r0 = strip * STRIP_ROWS;
    const int t = threadIdx.x;

    // Zero shared halo once: elements 0..3 and 260..263 of every field row, both buffers.
    if (t < 80) {
        int b = t / 40, rem = t % 40, f = rem / 8, e = rem % 8;
        Vs[b][f][(e < 4) ? e : (256 + e)] = 0ull;
    }

    const ull* __restrict__ p1 = (const ull*)img1 + (size_t)plane * (IMG_H * ROWU) + t;
    const ull* __restrict__ p2 = (const ull*)img2 + (size_t)plane * (IMG_H * ROWU) + t;

    const ull Wp[6] = {pack2(G0, G0), pack2(G1, G1), pack2(G2, G2),
                       pack2(G3, G3), pack2(G4, G4), pack2(G5, G5)};

    // 11-deep register ring buffers of the 5 fields (all indices static after unroll)
    ull X[11], Y[11], XX[11], YY[11], XY[11];

    auto loadrow = [&](int row, ull& a, ull& b) {
        if ((unsigned)row < IMG_H) {
            a = p1[(size_t)row * ROWU];
            b = p2[(size_t)row * ROWU];
        } else { a = 0ull; b = 0ull; }
    };

    // Prologue: fill slots 0..9 with input rows r0-5 .. r0+4 (zeros outside image)
#pragma unroll
    for (int p = 0; p < 10; ++p) {
        ull a, b; loadrow(r0 - 5 + p, a, b);
        X[p] = a; Y[p] = b;
        XX[p] = mul2(a, a); YY[p] = mul2(b, b); XY[p] = mul2(a, b);
    }
    ull na, nb;
    loadrow(r0 + 5, na, nb);                 // prefetch input row for first iteration

    __syncthreads();                         // halo zeros visible

    float accv = 0.0f;
    int buf = 0;

    for (int rr = 0; rr < STRIP_ROWS; rr += 11) {
#pragma unroll
        for (int ph = 0; ph < 11; ++ph) {
            // Consume prefetched input row (r0+5+rr+ph) into ring slot (10+ph)%11
            {
                const int slot = (10 + ph) % 11;
                ull a = na, b = nb;
                X[slot] = a; Y[slot] = b;
                XX[slot] = mul2(a, a); YY[slot] = mul2(b, b); XY[slot] = mul2(a, b);
            }
            // Prefetch next input row — latency covered by vertical+bar+horizontal work
            loadrow(r0 + 6 + rr + ph, na, nb);

            // Vertical 11-tap conv (packed f32x2 over the 2 owned columns)
            ull sx  = mul2(X[ph % 11],  Wp[0]);
            ull sy  = mul2(Y[ph % 11],  Wp[0]);
            ull sxx = mul2(XX[ph % 11], Wp[0]);
            ull syy = mul2(YY[ph % 11], Wp[0]);
            ull sxy = mul2(XY[ph % 11], Wp[0]);
#pragma unroll
            for (int k = 1; k <= 10; ++k) {
                const int s  = (ph + k) % 11;
                const int wi = (k < 6) ? k : 10 - k;
                sx  = fma2(X[s],  Wp[wi], sx);
                sy  = fma2(Y[s],  Wp[wi], sy);
                sxx = fma2(XX[s], Wp[wi], sxx);
                syy = fma2(YY[s], Wp[wi], syy);
                sxy = fma2(XY[s], Wp[wi], sxy);
            }

            ull* vb = &Vs[buf][0][0];
            vb[0 * 264 + 4 + t] = sx;
            vb[1 * 264 + 4 + t] = sy;
            vb[2 * 264 + 4 + t] = sxx;
            vb[3 * 264 + 4 + t] = syy;
            vb[4 * 264 + 4 + t] = sxy;
            __syncthreads();   // single bar/iter is safe with the 2-row double buffer

            // Horizontal conv + SSIM combine for output row rr+ph
            const float2* fb = (const float2*)vb;
            float mu1a, mu1b, mu2a, mu2b, exxa, exxb, eyya, eyyb, exya, exyb;
            hconv(fb + 0 * 264, t, mu1a, mu1b);
            hconv(fb + 1 * 264, t, mu2a, mu2b);
            hconv(fb + 2 * 264, t, exxa, exxb);
            hconv(fb + 3 * 264, t, eyya, eyyb);
            hconv(fb + 4 * 264, t, exya, exyb);

            if (r0 + rr + ph < IMG_H) {
                accv += ssim_px(mu1a, mu2a, exxa, eyya, exya);
                accv += ssim_px(mu1b, mu2b, exxb, eyyb, exyb);
            }
            buf ^= 1;
        }
    }

    // Deterministic block reduction -> fixed partial slot
#pragma unroll
    for (int off = 16; off; off >>= 1)
        accv += __shfl_xor_sync(0xffffffffu, accv, off);
    if ((t & 31) == 0) wsums[t >> 5] = accv;
    __syncthreads();
    if (t == 0) {
        float s = 0.0f;
#pragma unroll
        for (int i = 0; i < NTHREADS / 32; ++i) s += wsums[i];
        g_partials[bx] = (double)s;
    }
}

__global__ void ssim_finalize(float* __restrict__ out) {
    __shared__ double sh[64];
    int t = threadIdx.x;
    double s = 0.0;
    for (int i = t; i < NBLOCKS; i += 64) s += g_partials[i];
    sh[t] = s;
    __syncthreads();
    if (t < 32) {
        s = sh[t] + sh[t + 32];
#pragma unroll
        for (int off = 16; off; off >>= 1)
            s += __shfl_xor_sync(0xffffffffu, s, off);
        if (t == 0) out[0] = (float)(1.0 - s / 12582912.0);
    }
}

extern "C" void kernel_launch(void* const* d_in, const int* in_sizes, int n_in,
                              void* d_out, int out_size) {
    const float* img1 = (const float*)d_in[0];
    const float* img2 = (const float*)d_in[1];
    // d_in[2] (the gaussian window) is deterministic; weights are baked in as
    // immediates to get the FFMA-imm (rt=1) form.
    ssim_main<<<NBLOCKS, NTHREADS>>>(img1, img2);
    ssim_finalize<<<1, 64>>>((float*)d_out);
}

// round 2
// speedup vs baseline: 1.4174x; 1.4174x over previous
#include <cuda_runtime.h>

typedef unsigned long long ull;

#define IMG_W 512
#define IMG_H 512
#define NPLANES 48           // 16 batch * 3 channels
#define NSTRIPS 3
#define STRIP_ROWS 176       // 16 chunks of 11 rows
#define NBLOCKS (NPLANES * NSTRIPS)   // 144 -> single wave on 148/152 SMs
#define NTHREADS 256
#define ROWU 256             // float2 elements per 512-px image row
#define NCHUNKS 16

#define NFIELDS 5
#define VROWS 11
#define ROWF 528             // floats per V row: 8 left halo + 512 + 8 right halo
#define SMEM_FLOATS (NFIELDS * VROWS * ROWF)
#define SMEM_BYTES (SMEM_FLOATS * 4)   // 116160

#define SSIM_C1 0.0001f
#define SSIM_C2 0.0009f

// 1D gaussian (sigma=1.5, 11 taps, normalized) as literals -> FFMA-imm (rt=1)
#define G0 0.00102836f
#define G1 0.00759863f
#define G2 0.03600078f
#define G3 0.10936075f
#define G4 0.21300559f
#define G5 0.26601179f

__device__ double g_partials[NBLOCKS];
__device__ unsigned g_arrive = 0;

__device__ __forceinline__ ull pack2(float x, float y) {
    ull r; asm("mov.b64 %0, {%1,%2};" : "=l"(r) : "f"(x), "f"(y)); return r;
}
__device__ __forceinline__ ull mul2(ull a, ull b) {
    ull d; asm("mul.rn.f32x2 %0, %1, %2;" : "=l"(d) : "l"(a), "l"(b)); return d;
}
__device__ __forceinline__ ull fma2(ull a, ull b, ull c) {
    ull d; asm("fma.rn.f32x2 %0, %1, %2, %3;" : "=l"(d) : "l"(a), "l"(b), "l"(c)); return d;
}

// Horizontal 11-tap conv for 4 px (cols 4g..4g+3) from a V row.
// rp points at row float index 4g (= col 4g-8). All 5 float4 loads are 16B
// aligned and lane-contiguous (stride 16B) -> conflict-free LDS.128.
__device__ __forceinline__ void hconv4(const float* __restrict__ rp, float o[4]) {
    float e[20];
    const float4* q = (const float4*)rp;
#pragma unroll
    for (int i = 0; i < 5; ++i) {
        float4 v = q[i];
        e[4 * i] = v.x; e[4 * i + 1] = v.y; e[4 * i + 2] = v.z; e[4 * i + 3] = v.w;
    }
#pragma unroll
    for (int p = 0; p < 4; ++p) {
        float a = G0 * e[p + 3];
        a = fmaf(G1, e[p + 4], a);  a = fmaf(G2, e[p + 5], a);
        a = fmaf(G3, e[p + 6], a);  a = fmaf(G4, e[p + 7], a);
        a = fmaf(G5, e[p + 8], a);  a = fmaf(G4, e[p + 9], a);
        a = fmaf(G3, e[p + 10], a); a = fmaf(G2, e[p + 11], a);
        a = fmaf(G1, e[p + 12], a); a = fmaf(G0, e[p + 13], a);
        o[p] = a;
    }
}

__device__ __forceinline__ float ssim_px(float mu1, float mu2, float exx,
                                         float eyy, float exy) {
    float m11 = mu1 * mu1;
    float m22 = mu2 * mu2;
    float m12 = mu1 * mu2;
    float s1  = exx - m11;
    float s2  = eyy - m22;
    float s12 = exy - m12;
    float num = fmaf(2.0f, m12, SSIM_C1) * fmaf(2.0f, s12, SSIM_C2);
    float den = ((m11 + m22) + SSIM_C1) * ((s1 + s2) + SSIM_C2);
    return __fdividef(num, den);
}

__global__ void __launch_bounds__(NTHREADS, 1)
ssim_main(const float* __restrict__ img1, const float* __restrict__ img2,
          float* __restrict__ out) {
    extern __shared__ float Vs[];
    __shared__ float wsums[NTHREADS / 32];
    __shared__ int is_last;

    const int bx = blockIdx.x;
    const int plane = bx / NSTRIPS;
    const int strip = bx - plane * NSTRIPS;
    const int r0 = strip * STRIP_ROWS;
    const int t = threadIdx.x;

    // Zero halos: per (field,row), floats [0..7] (cols -8..-1) and [520..527] (cols 512..519)
    for (int idx = t; idx < NFIELDS * VROWS * 16; idx += NTHREADS) {
        int fr = idx >> 4, e = idx & 15;
        Vs[fr * ROWF + ((e < 8) ? e : (512 + e))] = 0.0f;
    }

    const ull* __restrict__ p1 = (const ull*)img1 + (size_t)plane * (IMG_H * ROWU) + t;
    const ull* __restrict__ p2 = (const ull*)img2 + (size_t)plane * (IMG_H * ROWU) + t;

    const ull Wp[6] = {pack2(G0, G0), pack2(G1, G1), pack2(G2, G2),
                       pack2(G3, G3), pack2(G4, G4), pack2(G5, G5)};

    // 11-deep register rings of the 5 product fields + next-chunk input staging
    ull X[11], Y[11], XX[11], YY[11], XY[11];
    ull nx[11], ny[11];

    auto loadrow = [&](int row, ull& a, ull& b) {
        if ((unsigned)row < IMG_H) {
            a = p1[(size_t)row * ROWU];
            b = p2[(size_t)row * ROWU];
        } else { a = 0ull; b = 0ull; }
    };

    // Prologue: slots 0..9 <- input rows r0-5 .. r0+4; stage rows r0+5..r0+15
#pragma unroll
    for (int s = 0; s < 10; ++s) {
        ull a, b; loadrow(r0 - 5 + s, a, b);
        X[s] = a; Y[s] = b;
        XX[s] = mul2(a, a); YY[s] = mul2(b, b); XY[s] = mul2(a, b);
    }
#pragma unroll
    for (int i = 0; i < 11; ++i) loadrow(r0 + 5 + i, nx[i], ny[i]);

    __syncthreads();   // halo zeros visible

    float accv = 0.0f;

    for (int c = 0; c < NCHUNKS; ++c) {
        const int R = r0 + c * 11;   // first output row of this chunk

        // ---- Vertical: 11 rows, ring indices static after unroll ----
#pragma unroll
        for (int i = 0; i < 11; ++i) {
            {
                const int slot = (10 + i) % 11;
                ull a = nx[i], b = ny[i];
                X[slot] = a; Y[slot] = b;
                XX[slot] = mul2(a, a); YY[slot] = mul2(b, b); XY[slot] = mul2(a, b);
            }
            ull sx  = mul2(X[i],  Wp[0]);
            ull sy  = mul2(Y[i],  Wp[0]);
            ull sxx = mul2(XX[i], Wp[0]);
            ull syy = mul2(YY[i], Wp[0]);
            ull sxy = mul2(XY[i], Wp[0]);
#pragma unroll
            for (int k = 1; k <= 10; ++k) {
                const int s  = (i + k) % 11;
                const int wi = (k < 6) ? k : 10 - k;
                sx  = fma2(X[s],  Wp[wi], sx);
                sy  = fma2(Y[s],  Wp[wi], sy);
                sxx = fma2(XX[s], Wp[wi], sxx);
                syy = fma2(YY[s], Wp[wi], syy);
                sxy = fma2(XY[s], Wp[wi], sxy);
            }
            const int off = i * ROWF + 8 + 2 * t;     // 8B-aligned (byte 32 + 8t)
            *(ull*)(Vs + 0 * VROWS * ROWF + off) = sx;
            *(ull*)(Vs + 1 * VROWS * ROWF + off) = sy;
            *(ull*)(Vs + 2 * VROWS * ROWF + off) = sxx;
            *(ull*)(Vs + 3 * VROWS * ROWF + off) = syy;
            *(ull*)(Vs + 4 * VROWS * ROWF + off) = sxy;
        }

        // Stage next chunk's inputs now; latency covered by bar + horizontal phase
        if (c + 1 < NCHUNKS) {
#pragma unroll
            for (int i = 0; i < 11; ++i) loadrow(R + 16 + i, nx[i], ny[i]);
        }

        __syncthreads();   // V rows visible

        // ---- Horizontal + SSIM: 11 rows x 128 groups of 4 px = 1408 jobs ----
        for (int j = 0; j < 6; ++j) {
            const int job = t + j * NTHREADS;
            if (job < VROWS * 128) {
                const int row = job >> 7;
                const int g = job & 127;
                const float* base = Vs + row * ROWF + 4 * g;
                float m1[4], m2[4], xx[4], yy[4], xy[4];
                hconv4(base + 0 * VROWS * ROWF, m1);
                hconv4(base + 1 * VROWS * ROWF, m2);
                hconv4(base + 2 * VROWS * ROWF, xx);
                hconv4(base + 3 * VROWS * ROWF, yy);
                hconv4(base + 4 * VROWS * ROWF, xy);
                if (R + row < IMG_H) {
#pragma unroll
                    for (int p = 0; p < 4; ++p)
                        accv += ssim_px(m1[p], m2[p], xx[p], yy[p], xy[p]);
                }
            }
        }
        __syncthreads();   // horizontal reads done before next chunk's STS
    }

    // ---- Deterministic block reduction ----
#pragma unroll
    for (int off = 16; off; off >>= 1)
        accv += __shfl_xor_sync(0xffffffffu, accv, off);
    if ((t & 31) == 0) wsums[t >> 5] = accv;
    __syncthreads();
    if (t == 0) {
        float s = 0.0f;
#pragma unroll
        for (int i = 0; i < NTHREADS / 32; ++i) s += wsums[i];
        g_partials[bx] = (double)s;
        __threadfence();
        unsigned old = atomicAdd(&g_arrive, 1u);
        is_last = (old == NBLOCKS - 1) ? 1 : 0;
    }
    __syncthreads();

    // ---- Fused deterministic finalize (last-arriving block, warp 0) ----
    if (is_last && t < 32) {
        __threadfence();
        double s = g_partials[t] + g_partials[t + 32] + g_partials[t + 64] +
                   g_partials[t + 96];
        if (t < NBLOCKS - 128) s += g_partials[t + 128];
#pragma unroll
        for (int off = 16; off; off >>= 1)
            s += __shfl_xor_sync(0xffffffffu, s, off);
        if (t == 0) {
            out[0] = (float)(1.0 - s / 12582912.0);   // 16*3*512*512
            g_arrive = 0;   // reset for next graph replay
        }
    }
}

extern "C" void kernel_launch(void* const* d_in, const int* in_sizes, int n_in,
                              void* d_out, int out_size) {
    const float* img1 = (const float*)d_in[0];
    const float* img2 = (const float*)d_in[1];
    // d_in[2] (gaussian window) is deterministic; weights baked in as immediates.
    cudaFuncSetAttribute(ssim_main, cudaFuncAttributeMaxDynamicSharedMemorySize,
                         SMEM_BYTES);
    ssim_main<<<NBLOCKS, NTHREADS, SMEM_BYTES>>>(img1, img2, (float*)d_out);
}